// round 17
// baseline (speedup 1.0000x reference)
#include <cuda_runtime.h>
#include <cuda_fp16.h>
#include <math.h>
#include <stdint.h>

#define T_STEPS 512
#define BATCH   64
#define DIM     1024
#define HID     1024
#define N4      4096                 // 4 * HID
#define M_TOT   (T_STEPS * BATCH)    // 32768
#define NBLK    128                  // persistent blocks (<=148 SMs, 1/SM)

// ---------------- scratch (static device globals; no runtime allocation) ----
__device__ float g_Xp[(size_t)M_TOT * N4];   // 512 MB: X @ Wx + b, [T*B, 4H]
__device__ float g_C[BATCH * HID];           // cell state
__device__ uint32_t g_Hh[BATCH * HID / 2];   // H(t) as packed half2 [row][k/2]
__device__ unsigned int g_bar;               // software grid barrier counter

// ---------------- init: cell state, H0 half2 staging, barrier ----------------
__global__ void init_c_kernel(const float* __restrict__ C0,
                              const float* __restrict__ H0) {
    int i = blockIdx.x * 256 + threadIdx.x;
    if (i < BATCH * HID) g_C[i] = C0[i];
    if (i < BATCH * HID / 2) {
        __half2 h = __floats2half2_rn(H0[2 * i], H0[2 * i + 1]);
        g_Hh[i] = *(uint32_t*)&h;
    }
    if (i == 0) g_bar = 0u;
}

// ---------------- helpers ----------------------------------------------------
__device__ __forceinline__ uint32_t pack_h2(float lo, float hi) {
    __half2 h = __floats2half2_rn(lo, hi);
    return *(uint32_t*)&h;
}

__device__ __forceinline__ void mma_f16(float& c0, float& c1, float& c2, float& c3,
                                        uint32_t a0, uint32_t a1, uint32_t a2, uint32_t a3,
                                        uint32_t b0, uint32_t b1) {
    asm volatile(
        "mma.sync.aligned.m16n8k16.row.col.f32.f16.f16.f32 "
        "{%0,%1,%2,%3}, {%4,%5,%6,%7}, {%8,%9}, {%0,%1,%2,%3};\n"
        : "+f"(c0), "+f"(c1), "+f"(c2), "+f"(c3)
        : "r"(a0), "r"(a1), "r"(a2), "r"(a3), "r"(b0), "r"(b1));
}

__device__ __forceinline__ unsigned bar_ld_acquire(const unsigned* p) {
    unsigned v;
    asm volatile("ld.global.acquire.gpu.u32 %0, [%1];" : "=r"(v) : "l"(p) : "memory");
    return v;
}
__device__ __forceinline__ void bar_red_release(unsigned* p, unsigned v) {
    asm volatile("red.release.gpu.global.add.u32 [%0], %1;" :: "l"(p), "r"(v) : "memory");
}

// ---------------- big GEMM (fp16 tensor cores): g_Xp = X @ Wx + b ------------
// (unchanged from R16: BK=32, k-pair smem layout, pad 18)
__global__ __launch_bounds__(256)
void xproj_f16_kernel(const float* __restrict__ X,
                      const float* __restrict__ W0, const float* __restrict__ W1,
                      const float* __restrict__ W2, const float* __restrict__ W3,
                      const float* __restrict__ b0, const float* __restrict__ b1,
                      const float* __restrict__ b2, const float* __restrict__ b3) {
    const int bn = blockIdx.x * 128;
    const int bm = blockIdx.y * 128;
    const int gate = bn >> 10;
    const float* W  = (gate == 0) ? W0 : (gate == 1) ? W1 : (gate == 2) ? W2 : W3;
    const float* bb = (gate == 0) ? b0 : (gate == 1) ? b1 : (gate == 2) ? b2 : b3;
    const int col0 = bn & (HID - 1);

    __shared__ uint32_t As[2][128][18];
    __shared__ uint32_t Bs[2][128][18];

    const int tid  = threadIdx.x;
    const int lane = tid & 31;
    const int warp = tid >> 5;
    const int wm   = warp >> 2;
    const int wn   = warp & 3;
    const int qg   = lane >> 2;
    const int qk   = lane & 3;

    const int ar = tid >> 1;
    const int ca = tid & 1;
    const int bc = tid & 127;
    const int cb = tid >> 7;

    float c[4][4][4];
    #pragma unroll
    for (int mt = 0; mt < 4; mt++)
        #pragma unroll
        for (int nt = 0; nt < 4; nt++)
            #pragma unroll
            for (int r = 0; r < 4; r++) c[mt][nt][r] = 0.0f;

    {
        #pragma unroll
        for (int i = 0; i < 4; i++) {
            float4 av = *(const float4*)&X[(size_t)(bm + ar) * DIM + 16 * ca + 4 * i];
            const int j0 = 2 * i, j1 = 2 * i + 1;
            As[0][ar][8 * ca + 2 * (j0 & 3) + (j0 >> 2)] = pack_h2(av.x, av.y);
            As[0][ar][8 * ca + 2 * (j1 & 3) + (j1 >> 2)] = pack_h2(av.z, av.w);
        }
        #pragma unroll
        for (int j = 0; j < 8; j++) {
            const int kr = 16 * cb + 2 * j;
            float lo = W[(size_t)kr       * HID + col0 + bc];
            float hi = W[(size_t)(kr + 1) * HID + col0 + bc];
            Bs[0][bc][8 * cb + 2 * (j & 3) + (j >> 2)] = pack_h2(lo, hi);
        }
    }
    __syncthreads();

    int buf = 0;
    for (int kt = 0; kt < DIM / 32; kt++) {
        float4 av[4];
        float blo[8], bhi[8];
        const int k0n = (kt + 1) * 32;
        const bool has_next = (kt + 1 < DIM / 32);
        if (has_next) {
            #pragma unroll
            for (int i = 0; i < 4; i++)
                av[i] = *(const float4*)&X[(size_t)(bm + ar) * DIM + k0n + 16 * ca + 4 * i];
            #pragma unroll
            for (int j = 0; j < 8; j++) {
                const int kr = k0n + 16 * cb + 2 * j;
                blo[j] = W[(size_t)kr       * HID + col0 + bc];
                bhi[j] = W[(size_t)(kr + 1) * HID + col0 + bc];
            }
        }

        #pragma unroll
        for (int ch = 0; ch < 2; ch++) {
            uint2 a0p[4], a1p[4];
            #pragma unroll
            for (int mt = 0; mt < 4; mt++) {
                const int m = wm * 64 + mt * 16;
                a0p[mt] = *(const uint2*)&As[buf][m + qg][8 * ch + 2 * qk];
                a1p[mt] = *(const uint2*)&As[buf][m + qg + 8][8 * ch + 2 * qk];
            }
            uint2 bp[4];
            #pragma unroll
            for (int nt = 0; nt < 4; nt++) {
                const int n = wn * 32 + nt * 8;
                bp[nt] = *(const uint2*)&Bs[buf][n + qg][8 * ch + 2 * qk];
            }
            #pragma unroll
            for (int mt = 0; mt < 4; mt++)
                #pragma unroll
                for (int nt = 0; nt < 4; nt++)
                    mma_f16(c[mt][nt][0], c[mt][nt][1], c[mt][nt][2], c[mt][nt][3],
                            a0p[mt].x, a1p[mt].x, a0p[mt].y, a1p[mt].y,
                            bp[nt].x, bp[nt].y);
        }

        if (has_next) {
            const int nb = buf ^ 1;
            #pragma unroll
            for (int i = 0; i < 4; i++) {
                const int j0 = 2 * i, j1 = 2 * i + 1;
                As[nb][ar][8 * ca + 2 * (j0 & 3) + (j0 >> 2)] = pack_h2(av[i].x, av[i].y);
                As[nb][ar][8 * ca + 2 * (j1 & 3) + (j1 >> 2)] = pack_h2(av[i].z, av[i].w);
            }
            #pragma unroll
            for (int j = 0; j < 8; j++)
                Bs[nb][bc][8 * cb + 2 * (j & 3) + (j >> 2)] = pack_h2(blo[j], bhi[j]);
            __syncthreads();
            buf = nb;
        }
    }

    #pragma unroll
    for (int mt = 0; mt < 4; mt++) {
        #pragma unroll
        for (int nt = 0; nt < 4; nt++) {
            const int colg = wn * 32 + nt * 8 + 2 * qk;
            const float bx0 = bb[col0 + colg];
            const float bx1 = bb[col0 + colg + 1];
            const size_t row0 = (size_t)(bm + wm * 64 + mt * 16 + qg);
            float2 v0 = make_float2(c[mt][nt][0] + bx0, c[mt][nt][1] + bx1);
            float2 v1 = make_float2(c[mt][nt][2] + bx0, c[mt][nt][3] + bx1);
            *(float2*)&g_Xp[row0 * N4 + bn + colg]       = v0;
            *(float2*)&g_Xp[(row0 + 8) * N4 + bn + colg] = v1;
        }
    }
}

// ---------------- persistent recurrence kernel (fp16 m16n8k16) ---------------
// 128 blocks x 512 threads (16 warps), 1 block/SM. K split 4-way: kg = warp>>2
// covers half2-K [kg*128, kg*128+128); warp quad (2x2) per K-group. Per-warp
// mma count 64/step. K-tile = 32 fp32 (16 half2) per group, 8 tiles -> 8
// syncs/step. Epilogue (tid < 256) sums 4 partials.
//
// Wp[kc16=64][qk=4][gc pad 35][slot 2] : 71,680 B
// As[kg=4][buf=2][m=64][16 pad 18]     : 36,864 B
// sg[kg=4][row=64][gc pad 33]          : 33,792 B    = 142,336 B
#define WP_WORDS (64 * 4 * 35 * 2)
#define AS_WORDS (4 * 2 * 64 * 18)
#define SG_WORDS (4 * 64 * 33)
#define SMEM_BYTES ((WP_WORDS + AS_WORDS + SG_WORDS) * 4)

__global__ __launch_bounds__(512)
void lstm_persistent(const float* __restrict__ W0, const float* __restrict__ W1,
                     const float* __restrict__ W2, const float* __restrict__ W3,
                     float* __restrict__ out) {
    extern __shared__ unsigned char smem_raw[];
    uint32_t (*Wp)[4][35][2]  = (uint32_t (*)[4][35][2])smem_raw;
    uint32_t (*As)[2][64][18] = (uint32_t (*)[2][64][18])(smem_raw + WP_WORDS * 4);
    float    (*sg)[64][33]    = (float (*)[64][33])(smem_raw + (WP_WORDS + AS_WORDS) * 4);

    const int tid  = threadIdx.x;
    const int lane = tid & 31;
    const int warp = tid >> 5;           // 0..15
    const int colbase = blockIdx.x * 8;

    const float* Wg[4] = {W0, W1, W2, W3};

    const int kg = warp >> 2;            // K-group 0..3
    const int wq = warp & 3;
    const int wm = wq >> 1;              // rows 32*wm
    const int wn = wq & 1;               // gate-cols 16*wn
    const int qg = lane >> 2;
    const int qk = lane & 3;

    // H loader mapping: 128 threads per K-group (tid>>7 == kg)
    const int gtid = tid & 127;
    const int k2 = gtid & 15;            // half2 index within tile (0..15)
    const int rh = gtid >> 4;            // rows rh + 8i
    const int apos = ((k2 >> 3) << 3) | ((k2 & 3) << 1) | ((k2 >> 2) & 1);

    // epilogue mapping (tid < 256): 2 adjacent cells per thread
    const int erow = (tid & 255) >> 2;   // 0..63
    const int ecc  = (tid & 3) * 2;      // 0,2,4,6
    const size_t xpb = (size_t)erow * N4 + colbase + ecc;
    const bool epi = (tid < 256);

    // ---- load resident W (once) as half2 pairs ----
    {
        const int gc  = tid & 31;
        const int g   = gc >> 3;
        const int cl  = gc & 7;
        const int khb = (tid >> 5) * 32;     // 16 warps x 32 half2 k-rows
        for (int j = 0; j < 32; j++) {
            const int kh = khb + j;
            const int k  = kh * 2;
            const float lo = Wg[g][(size_t)k * HID + colbase + cl];
            const float hi = Wg[g][(size_t)(k + 1) * HID + colbase + cl];
            const int kc16 = kh >> 3;
            const int win  = kh & 7;
            Wp[kc16][win & 3][gc][win >> 2] = pack_h2(lo, hi);
        }
    }
    __syncthreads();

    // ---- prefetch Xp for step 0 ----
    float2 xp[4];
    if (epi) {
        #pragma unroll
        for (int g = 0; g < 4; g++)
            xp[g] = *(const float2*)&g_Xp[xpb + (size_t)g * HID];
    }

    for (int t = 0; t < T_STEPS; t++) {
        float* Hout = out + (size_t)t * BATCH * HID;

        float c[2][2][4];
        #pragma unroll
        for (int mt = 0; mt < 2; mt++)
            #pragma unroll
            for (int nt = 0; nt < 2; nt++)
                #pragma unroll
                for (int r = 0; r < 4; r++) c[mt][nt][r] = 0.0f;

        const int khbase = kg * 128;     // this group's half2-K origin

        // preload H k-tile 0 (raw u32 half2 from g_Hh): 8 rows per thread
        #pragma unroll
        for (int i = 0; i < 8; i++) {
            const int row = rh + 8 * i;
            As[kg][0][row][apos] = __ldcg(&g_Hh[row * 512 + khbase + k2]);
        }
        __syncthreads();

        int buf = 0;
        for (int kt = 0; kt < 8; kt++) {
            uint32_t hreg[8];
            const bool has_next = (kt + 1 < 8);
            if (has_next) {
                const int kh0 = khbase + (kt + 1) * 16;
                #pragma unroll
                for (int i = 0; i < 8; i++)
                    hreg[i] = __ldcg(&g_Hh[(rh + 8 * i) * 512 + kh0 + k2]);
            }

            // compute on buf: 2 chunks of K=16
            #pragma unroll
            for (int ch = 0; ch < 2; ch++) {
                const int kc16 = kg * 16 + kt * 2 + ch;
                uint2 a01[2], a23[2];
                #pragma unroll
                for (int mt = 0; mt < 2; mt++) {
                    const int m = 32 * wm + 16 * mt;
                    a01[mt] = *(const uint2*)&As[kg][buf][m + qg][ch * 8 + 2 * qk];
                    a23[mt] = *(const uint2*)&As[kg][buf][m + qg + 8][ch * 8 + 2 * qk];
                }
                uint2 bp[2];
                #pragma unroll
                for (int nt = 0; nt < 2; nt++) {
                    const int n = 16 * wn + 8 * nt;
                    bp[nt] = *(const uint2*)&Wp[kc16][qk][n + qg][0];
                }
                #pragma unroll
                for (int mt = 0; mt < 2; mt++)
                    #pragma unroll
                    for (int nt = 0; nt < 2; nt++)
                        mma_f16(c[mt][nt][0], c[mt][nt][1], c[mt][nt][2], c[mt][nt][3],
                                a01[mt].x, a23[mt].x, a01[mt].y, a23[mt].y,
                                bp[nt].x, bp[nt].y);
            }

            if (has_next) {
                const int nb = buf ^ 1;
                #pragma unroll
                for (int i = 0; i < 8; i++)
                    As[kg][nb][rh + 8 * i][apos] = hreg[i];
                __syncthreads();
                buf = nb;
            }
        }

        // stash per-K-group gate partials
        #pragma unroll
        for (int mt = 0; mt < 2; mt++) {
            #pragma unroll
            for (int nt = 0; nt < 2; nt++) {
                const int row = 32 * wm + 16 * mt + qg;
                const int cn  = 16 * wn + 8 * nt + 2 * qk;
                sg[kg][row][cn]         = c[mt][nt][0];
                sg[kg][row][cn + 1]     = c[mt][nt][1];
                sg[kg][row + 8][cn]     = c[mt][nt][2];
                sg[kg][row + 8][cn + 1] = c[mt][nt][3];
            }
        }
        __syncthreads();

        // ---- fused LSTM cell epilogue: tid<256, 2 adjacent cells each ----
        if (epi) {
            const int idx = erow * HID + colbase + ecc;
            float2 cprev = *(const float2*)&g_C[idx];
            float hv[2], cv[2];
            #pragma unroll
            for (int s = 0; s < 2; s++) {
                const int cc = ecc + s;
                float gi = (sg[0][erow][0  + cc] + sg[1][erow][0  + cc])
                         + (sg[2][erow][0  + cc] + sg[3][erow][0  + cc]) + (s ? xp[0].y : xp[0].x);
                float gf = (sg[0][erow][8  + cc] + sg[1][erow][8  + cc])
                         + (sg[2][erow][8  + cc] + sg[3][erow][8  + cc]) + (s ? xp[1].y : xp[1].x);
                float go = (sg[0][erow][16 + cc] + sg[1][erow][16 + cc])
                         + (sg[2][erow][16 + cc] + sg[3][erow][16 + cc]) + (s ? xp[2].y : xp[2].x);
                float gg = (sg[0][erow][24 + cc] + sg[1][erow][24 + cc])
                         + (sg[2][erow][24 + cc] + sg[3][erow][24 + cc]) + (s ? xp[3].y : xp[3].x);

                float I = 1.0f / (1.0f + __expf(-gi));
                float F = 1.0f / (1.0f + __expf(-gf));
                float O = 1.0f / (1.0f + __expf(-go));
                float G = tanhf(gg);

                cv[s] = fmaf(F, (s ? cprev.y : cprev.x), I * G);
                hv[s] = O * tanhf(cv[s]);
            }
            *(float2*)&g_C[idx] = make_float2(cv[0], cv[1]);
            __stcg((float2*)&Hout[idx], make_float2(hv[0], hv[1]));
            __stcg(&g_Hh[erow * 512 + ((colbase + ecc) >> 1)], pack_h2(hv[0], hv[1]));
        }

        // ---- prefetch next step's Xp (read-only; overlaps barrier wait) ----
        if (epi && t + 1 < T_STEPS) {
            const float* Xp_n = g_Xp + (size_t)(t + 1) * BATCH * N4;
            #pragma unroll
            for (int g = 0; g < 4; g++)
                xp[g] = *(const float2*)&Xp_n[xpb + (size_t)g * HID];
        }

        // ---- grid barrier (canonical CG pattern) ----
        __syncthreads();
        if (tid == 0) {
            bar_red_release(&g_bar, 1u);
            const unsigned target = (unsigned)NBLK * (unsigned)(t + 1);
            while (bar_ld_acquire(&g_bar) < target) {}
        }
        __syncthreads();
    }
}

// ---------------- tail: H_f and C_f after outputs ---------------------------
__global__ void finalize_kernel(float* __restrict__ out) {
    int i = blockIdx.x * 256 + threadIdx.x;
    if (i < BATCH * HID) {
        size_t base = (size_t)T_STEPS * BATCH * HID;
        out[base + i] = out[(size_t)(T_STEPS - 1) * BATCH * HID + i];  // H_f
        out[base + BATCH * HID + i] = g_C[i];                          // C_f
    }
}

// ---------------- launch -----------------------------------------------------
extern "C" void kernel_launch(void* const* d_in, const int* in_sizes, int n_in,
                              void* d_out, int out_size) {
    const float* X   = (const float*)d_in[0];
    const float* H0  = (const float*)d_in[1];
    const float* C0  = (const float*)d_in[2];
    const float* Wxi = (const float*)d_in[3];
    const float* Wxf = (const float*)d_in[4];
    const float* Wxo = (const float*)d_in[5];
    const float* Wxc = (const float*)d_in[6];
    const float* Whi = (const float*)d_in[7];
    const float* Whf = (const float*)d_in[8];
    const float* Who = (const float*)d_in[9];
    const float* Whc = (const float*)d_in[10];
    const float* bi  = (const float*)d_in[11];
    const float* bf  = (const float*)d_in[12];
    const float* bo  = (const float*)d_in[13];
    const float* bc  = (const float*)d_in[14];
    float* out = (float*)d_out;

    cudaFuncSetAttribute(lstm_persistent,
                         cudaFuncAttributeMaxDynamicSharedMemorySize, SMEM_BYTES);

    init_c_kernel<<<256, 256>>>(C0, H0);
    xproj_f16_kernel<<<dim3(32, 256), 256>>>(X, Wxi, Wxf, Wxo, Wxc,
                                             bi, bf, bo, bc);
    lstm_persistent<<<NBLK, 512, SMEM_BYTES>>>(Whi, Whf, Who, Whc, out);
    finalize_kernel<<<256, 256>>>(out);
}